// round 7
// baseline (speedup 1.0000x reference)
#include <cuda_runtime.h>

typedef unsigned long long u64;
typedef unsigned int u32;

#define NEG_INF_F (-3.4028234663852886e38f)
#define CAP   4096
#define HCAP  4096
#define NTH   1024
#define LOCAL (CAP/NTH)
#define TOPN  64
#define PRNG_SCHEME 2   // 2 = partitionable (xor-fold, modern JAX default), 1 = legacy split-half

__device__ __forceinline__ u32 fkey(float f){
  u32 u = __float_as_uint(f);
  return (u & 0x80000000u) ? ~u : (u | 0x80000000u);
}
__device__ __forceinline__ float fdec(u32 s){
  u32 u = (s & 0x80000000u) ? (s ^ 0x80000000u) : ~s;
  return __uint_as_float(u);
}
__device__ __forceinline__ void tfb(u32& x0, u32& x1, int r0, int r1, int r2, int r3){
  x0 += x1; x1 = __funnelshift_l(x1, x1, r0); x1 ^= x0;
  x0 += x1; x1 = __funnelshift_l(x1, x1, r1); x1 ^= x0;
  x0 += x1; x1 = __funnelshift_l(x1, x1, r2); x1 ^= x0;
  x0 += x1; x1 = __funnelshift_l(x1, x1, r3); x1 ^= x0;
}
// threefry2x32, key = (0,42)  == jax.random.key(42)
__device__ __forceinline__ void threefry42(u32 c0, u32 c1, u32& o0, u32& o1){
  const u32 k0 = 0u, k1 = 42u, k2 = 0x1BD11BDAu ^ k0 ^ k1;
  u32 x0 = c0 + k0, x1 = c1 + k1;
  tfb(x0,x1,13,15,26,6);  x0 += k1; x1 += k2 + 1u;
  tfb(x0,x1,17,29,16,24); x0 += k2; x1 += k0 + 2u;
  tfb(x0,x1,13,15,26,6);  x0 += k0; x1 += k1 + 3u;
  tfb(x0,x1,17,29,16,24); x0 += k1; x1 += k2 + 4u;
  tfb(x0,x1,13,15,26,6);  x0 += k2; x1 += k0 + 5u;
  o0 = x0; o1 = x1;
}
__device__ __forceinline__ float gumbel_at(u64 j, u64 half){
  u32 o0, o1, bits;
#if PRNG_SCHEME == 1
  if (j < half){ threefry42((u32)j, (u32)(j + half), o0, o1); bits = o0; }
  else         { threefry42((u32)(j - half), (u32)j, o0, o1); bits = o1; }
#else
  threefry42((u32)(j >> 32), (u32)j, o0, o1); bits = o0 ^ o1;
#endif
  float u = __uint_as_float((bits >> 9) | 0x3f800000u) - 1.0f;
  float v = fmaxf(1e-10f, u + 1e-10f);   // (1-1e-10)==1 in fp32
  return -logf(-logf(v));
}

__global__ void __launch_bounds__(NTH, 1)
sampler_kernel(const float* __restrict__ logits, const float* __restrict__ temperature,
               const float* __restrict__ presence, const float* __restrict__ frequency,
               const float* __restrict__ repetition, const float* __restrict__ top_p,
               const int* __restrict__ prompt_ids, const int* __restrict__ out_tok,
               const int* __restrict__ out_lens, const int* __restrict__ stop_ids,
               const int* __restrict__ min_toks, const int* __restrict__ top_k,
               float* __restrict__ out, int B, int V, int P, int O, int S, int MN,
               int nchunk)
{
  extern __shared__ unsigned char smraw[];
  u64* cand = (u64*)smraw;              // CAP
  u32* hkey = (u32*)(cand + CAP);       // HCAP
  u32* hval = hkey + HCAP;              // HCAP
  float* chmax = (float*)(hval + HCAP); // nchunk (per-32-element chunk maxima)
  __shared__ u64 red64[32];
  __shared__ volatile u64 sh_win;
  __shared__ float redm[32], reds[32], redsum[32], redsq[32];
  __shared__ float sh_m, sh_logs, sh_T, sh_lo, sh_hi;
  __shared__ int sh_cnt;

  const int tid = threadIdx.x, row = blockIdx.x;
  const int lane = tid & 31, wid = tid >> 5;
  const float* lrow = logits + (size_t)row * V;

  // penalty-state hash: bits[0:16) output count, bit16 prompt-seen, bit17 stop-neg
  for (int i = tid; i < HCAP; i += NTH){ hkey[i] = 0xFFFFFFFFu; hval[i] = 0u; }
  __syncthreads();
  const int olen = out_lens[row];
  const bool penal = olen < min_toks[row];
  auto insert = [&](int id, u32 orb, u32 add){
    u32 uid = (u32)id, h = ((uid * 2654435761u) >> 16) & (HCAP - 1);
    for (;;){
      u32 k = hkey[h];
      if (k == uid) break;
      if (k == 0xFFFFFFFFu){
        u32 old = atomicCAS(&hkey[h], 0xFFFFFFFFu, uid);
        if (old == 0xFFFFFFFFu || old == uid) break;
      }
      h = (h + 1) & (HCAP - 1);
    }
    if (orb) atomicOr(&hval[h], orb);
    if (add) atomicAdd(&hval[h], add);
  };
  for (int i = tid; i < P; i += NTH) insert(prompt_ids[(size_t)row*P + i], 1u<<16, 0u);
  for (int i = tid; i < O; i += NTH) if (i < olen) insert(out_tok[(size_t)row*O + i], 0u, 1u);
  if (penal) for (int i = tid; i < S; i += NTH) insert(stop_ids[(size_t)row*S + i], 1u<<17, 0u);
  __syncthreads();

  // pass 1: streaming max/sumexp + moments + per-chunk (32 elem) maxima
  float m = __int_as_float(0xff800000), s = 0.f, sum = 0.f, ssq = 0.f;
  const int n4 = V >> 2;
  const float4* l4 = (const float4*)lrow;
  const int iters = (n4 + NTH - 1) / NTH;
  for (int t = 0; t < iters; t++){
    int i = t * NTH + tid;
    bool in = (i < n4);
    float lm = __int_as_float(0xff800000);
    if (in){
      float4 v = l4[i];
      float xs[4] = {v.x, v.y, v.z, v.w};
      #pragma unroll
      for (int c2 = 0; c2 < 4; c2++){
        float x = xs[c2];
        if (x > m){ s = s * __expf(m - x) + 1.f; m = x; } else s += __expf(x - m);
        sum += x; ssq += x * x;
        lm = fmaxf(lm, x);
      }
    }
    // 8-lane subgroup max -> chunk max (chunk = 8 consecutive float4s)
    #pragma unroll
    for (int o = 1; o < 8; o <<= 1)
      lm = fmaxf(lm, __shfl_xor_sync(~0u, lm, o));
    if ((lane & 7) == 0 && in) chmax[i >> 3] = lm;
  }
  for (int i = (n4 << 2) + tid; i < V; i += NTH){
    float x = lrow[i];
    if (x > m){ s = s * __expf(m - x) + 1.f; m = x; } else s += __expf(x - m);
    sum += x; ssq += x * x;
  }
  #pragma unroll
  for (int o = 16; o; o >>= 1){
    float mo = __shfl_down_sync(~0u, m, o), so = __shfl_down_sync(~0u, s, o);
    float su = __shfl_down_sync(~0u, sum, o), sq = __shfl_down_sync(~0u, ssq, o);
    if (mo > m){ s = s * __expf(m - mo) + so; m = mo; } else if (so > 0.f) s += so * __expf(mo - m);
    sum += su; ssq += sq;
  }
  if (lane == 0){ redm[wid]=m; reds[wid]=s; redsum[wid]=sum; redsq[wid]=ssq; }
  __syncthreads();
  if (wid == 0){
    m = redm[lane]; s = reds[lane]; sum = redsum[lane]; ssq = redsq[lane];
    #pragma unroll
    for (int o = 16; o; o >>= 1){
      float mo = __shfl_down_sync(~0u, m, o), so = __shfl_down_sync(~0u, s, o);
      float su = __shfl_down_sync(~0u, sum, o), sq = __shfl_down_sync(~0u, ssq, o);
      if (mo > m){ s = s * __expf(m - mo) + so; m = mo; } else if (so > 0.f) s += so * __expf(mo - m);
      sum += su; ssq += sq;
    }
    if (lane == 0){
      sh_m = m; sh_logs = logf(s);
      float mu = sum / (float)V;
      float sig = sqrtf(fmaxf(ssq / (float)V - mu * mu, 0.f));
      float lo = mu - 4.0f * sig - 1e-6f, hi = m, T = mu + 2.0f * sig;
      if (!(T > lo)) T = lo;
      if (T > hi) T = 0.5f * (lo + hi);
      sh_lo = lo; sh_hi = hi; sh_T = T;
    }
  }
  __syncthreads();

  // threshold-gather: chunk-max skip + one shared atomic per warp per iter
  int minc = P + O + S + TOPN;
  if (minc > V) minc = V;
  int c = 0;
  for (int it = 0; it < 40; it++){
    if (tid == 0) sh_cnt = 0;
    __syncthreads();
    const float T = sh_T;
    for (int t = 0; t < iters; t++){         // warp-converged trip count
      int i = t * NTH + tid;
      bool in = (i < n4) && (chmax[(i < n4 ? i : 0) >> 3] >= T);
      float4 v = in ? l4[i] : make_float4(NEG_INF_F, NEG_INF_F, NEG_INF_F, NEG_INF_F);
      float xs[4] = {v.x, v.y, v.z, v.w};
      u32 mk[4]; int pc[4];
      #pragma unroll
      for (int c2 = 0; c2 < 4; c2++){
        mk[c2] = __ballot_sync(~0u, in && (xs[c2] >= T));
        pc[c2] = __popc(mk[c2]);
      }
      int total = pc[0] + pc[1] + pc[2] + pc[3];
      if (total){
        int base = 0;
        if (lane == 0) base = atomicAdd(&sh_cnt, total);
        base = __shfl_sync(~0u, base, 0);
        int run = 0, bi = i << 2;
        u32 lt = (1u << lane) - 1u;
        #pragma unroll
        for (int c2 = 0; c2 < 4; c2++){
          if (mk[c2] & (1u << lane)){
            int p = base + run + __popc(mk[c2] & lt);
            if (p < CAP) cand[p] = ((u64)fkey(xs[c2]) << 32) | (u32)~(u32)(bi + c2);
          }
          run += pc[c2];
        }
      }
    }
    for (int i = (n4<<2) + tid; i < V; i += NTH){   // scalar tail (V%4)
      float x = lrow[i];
      if (x >= T){ int p = atomicAdd(&sh_cnt,1); if (p < CAP) cand[p] = ((u64)fkey(x)<<32) | (u32)~(u32)i; }
    }
    __syncthreads();
    c = sh_cnt;
    if (c >= minc && c <= CAP) break;
    if (tid == 0){ if (c > CAP) sh_lo = sh_T; else sh_hi = sh_T; sh_T = 0.5f*(sh_lo + sh_hi); }
    __syncthreads();
  }
  if (c > CAP) c = CAP;

  u64 rk[LOCAL];
  #pragma unroll
  for (int q = 0; q < LOCAL; q++){ int p = q*NTH + tid; rk[q] = (p < c) ? cand[p] : 0ULL; }
  const float mrow = sh_m, logZ = sh_logs;

  // raw top-MN -> logprobs + indices (log_softmax monotone in raw logits)
  u32 rmask = 0;
  const int mrounds = (MN < c) ? MN : c;
  for (int r = 0; r < mrounds; r++){
    u64 b = 0;
    #pragma unroll
    for (int q = 0; q < LOCAL; q++) if (!((rmask>>q)&1u) && rk[q] > b) b = rk[q];
    u64 v = b;
    #pragma unroll
    for (int o = 16; o; o >>= 1){ u64 t = __shfl_down_sync(~0u, v, o); if (t > v) v = t; }
    if (lane == 0) red64[wid] = v;
    __syncthreads();
    if (wid == 0){
      u64 w = red64[lane];
      #pragma unroll
      for (int o = 16; o; o >>= 1){ u64 t = __shfl_down_sync(~0u, w, o); if (t > w) w = t; }
      if (lane == 0) sh_win = w;
    }
    __syncthreads();
    u64 win = sh_win;
    if (tid == 0){
      out[(size_t)B + (size_t)row*MN + r] = (fdec((u32)(win>>32)) - mrow) - logZ;
      out[(size_t)B + (size_t)B*MN + (size_t)row*MN + r] = (float)(~(u32)win);
    }
    #pragma unroll
    for (int q = 0; q < LOCAL; q++) if (rk[q] == win) rmask |= (1u<<q);
  }
  if (tid == 0) for (int r = mrounds; r < MN; r++){
    out[(size_t)B + (size_t)row*MN + r] = 0.f;
    out[(size_t)B + (size_t)B*MN + (size_t)row*MN + r] = 0.f;
  }

  // transform candidates: penalties + temperature (all non-increasing)
  const float rep = repetition[row], fr = frequency[row], pr = presence[row];
  const float tp = temperature[row], td = (tp < 1e-5f) ? 1.f : tp;
  __syncthreads();
  #pragma unroll
  for (int q = 0; q < LOCAL; q++){
    int p = q*NTH + tid;
    u64 k = rk[q];
    if (k != 0ULL){
      u32 idx = ~(u32)k;
      float x = fdec((u32)(k >> 32));
      u32 h = ((idx * 2654435761u) >> 16) & (HCAP - 1), info = 0;
      for (;;){
        u32 kk = hkey[h];
        if (kk == idx){ info = hval[h]; break; }
        if (kk == 0xFFFFFFFFu) break;
        h = (h + 1) & (HCAP - 1);
      }
      int cv = (int)(info & 0xFFFFu);
      if (info & (1u<<17)) x = NEG_INF_F;
      if ((info & (1u<<16)) || cv > 0) x = (x > 0.f) ? (x / rep) : (x * rep);
      x = x - fr * (float)cv;
      if (cv > 0) x = x - pr;
      x = x / td;
      k = ((u64)fkey(x) << 32) | (u32)~idx;
    }
    cand[p] = k;
  }

  // bitonic ascending sort of cand[0..CAP): largest ends at CAP-1
  for (int kk = 2; kk <= CAP; kk <<= 1)
    for (int j = kk >> 1; j > 0; j >>= 1){
      __syncthreads();
      for (int t = tid; t < CAP; t += NTH){
        int l = t ^ j;
        if (l > t){
          u64 a = cand[t], bb = cand[l];
          bool asc = ((t & kk) == 0);
          if (asc ? (a > bb) : (a < bb)){ cand[t] = bb; cand[l] = a; }
        }
      }
    }
  __syncthreads();

  // epilogue: top-k mask, top-p mask, gumbel-argmax (thread 0; <=64 survivors)
  if (tid == 0){
    const int trounds = (TOPN < c) ? TOPN : c;
    int k = top_k[row];
    if (k < 1) k = 1;
    if (k > trounds) k = trounds;
    float kth = fdec((u32)(cand[CAP - k] >> 32));
    float m0  = fdec((u32)(cand[CAP - 1] >> 32));
    float Ssum = 0.f; int k2 = 0;
    for (int j = 0; j < trounds; j++){
      float x = fdec((u32)(cand[CAP-1-j] >> 32));
      if (x >= kth){ Ssum += expf(x - m0); k2 = j + 1; } else break;
    }
    const float thr = top_p[row] * Ssum;
    const u64 half = ((u64)B * (u64)V) >> 1;
    float pref = 0.f, best = __int_as_float(0xff800000);
    u32 besti = ~(u32)cand[CAP - 1];
    for (int j = 0; j < k2; j++){
      u64 w = cand[CAP-1-j];
      float x = fdec((u32)(w >> 32));
      u32 ix = ~(u32)w;
      bool keep = (j == 0) || (pref < thr);
      pref += expf(x - m0);
      if (keep){
        float sc = x + gumbel_at((u64)row * (u64)V + ix, half);
        if (sc > best){ best = sc; besti = ix; }
      }
    }
    out[row] = (float)((tp < 1e-5f) ? (~(u32)cand[CAP - 1]) : besti);
  }
}

extern "C" void kernel_launch(void* const* d_in, const int* in_sizes, int n_in,
                              void* d_out, int out_size)
{
  const float* logits = (const float*)d_in[0];
  int B = in_sizes[1];
  int V = in_sizes[0] / B;
  int P = in_sizes[6] / B;
  int O = in_sizes[7] / B;
  int S = in_sizes[9] / B;
  int MN = (out_size / B - 1) / 2;
  if (MN < 0) MN = 0;
  int n4 = V >> 2;
  int nchunk = (n4 + 7) >> 3;
  size_t sh = (size_t)CAP * sizeof(u64) + (size_t)HCAP * 2 * sizeof(u32)
            + (size_t)nchunk * sizeof(float);
  cudaFuncSetAttribute(sampler_kernel, cudaFuncAttributeMaxDynamicSharedMemorySize, (int)sh);
  sampler_kernel<<<B, NTH, sh>>>(logits,
      (const float*)d_in[1], (const float*)d_in[2], (const float*)d_in[3],
      (const float*)d_in[4], (const float*)d_in[5],
      (const int*)d_in[6], (const int*)d_in[7], (const int*)d_in[8],
      (const int*)d_in[9], (const int*)d_in[10], (const int*)d_in[11],
      (float*)d_out, B, V, P, O, S, MN, nchunk);
}

// round 8
// speedup vs baseline: 1.2453x; 1.2453x over previous
#include <cuda_runtime.h>

typedef unsigned long long u64;
typedef unsigned int u32;

#define NEG_INF_F (-3.4028234663852886e38f)
#define CAP   4096
#define HCAP  4096
#define NTH   1024
#define LOCAL (CAP/NTH)
#define TOPN  64
#define SSZ   512
#define SPLIT 4
#define MAXB  256
#define MAXCHUNK 8192
#define PRNG_SCHEME 2   // 2 = partitionable (xor-fold, modern JAX default), 1 = legacy split-half

__device__ float g_smax[MAXB * SPLIT];
__device__ float g_ssum[MAXB * SPLIT];
__device__ float g_sssq[MAXB * SPLIT];
__device__ float g_sexp[MAXB * SPLIT];
__device__ float g_chmax[(size_t)MAXB * MAXCHUNK];

__device__ __forceinline__ u32 fkey(float f){
  u32 u = __float_as_uint(f);
  return (u & 0x80000000u) ? ~u : (u | 0x80000000u);
}
__device__ __forceinline__ float fdec(u32 s){
  u32 u = (s & 0x80000000u) ? (s ^ 0x80000000u) : ~s;
  return __uint_as_float(u);
}
__device__ __forceinline__ void tfb(u32& x0, u32& x1, int r0, int r1, int r2, int r3){
  x0 += x1; x1 = __funnelshift_l(x1, x1, r0); x1 ^= x0;
  x0 += x1; x1 = __funnelshift_l(x1, x1, r1); x1 ^= x0;
  x0 += x1; x1 = __funnelshift_l(x1, x1, r2); x1 ^= x0;
  x0 += x1; x1 = __funnelshift_l(x1, x1, r3); x1 ^= x0;
}
// threefry2x32, key = (0,42)  == jax.random.key(42)
__device__ __forceinline__ void threefry42(u32 c0, u32 c1, u32& o0, u32& o1){
  const u32 k0 = 0u, k1 = 42u, k2 = 0x1BD11BDAu ^ k0 ^ k1;
  u32 x0 = c0 + k0, x1 = c1 + k1;
  tfb(x0,x1,13,15,26,6);  x0 += k1; x1 += k2 + 1u;
  tfb(x0,x1,17,29,16,24); x0 += k2; x1 += k0 + 2u;
  tfb(x0,x1,13,15,26,6);  x0 += k0; x1 += k1 + 3u;
  tfb(x0,x1,17,29,16,24); x0 += k1; x1 += k2 + 4u;
  tfb(x0,x1,13,15,26,6);  x0 += k2; x1 += k0 + 5u;
  o0 = x0; o1 = x1;
}
__device__ __forceinline__ float gumbel_at(u64 j, u64 half){
  u32 o0, o1, bits;
#if PRNG_SCHEME == 1
  if (j < half){ threefry42((u32)j, (u32)(j + half), o0, o1); bits = o0; }
  else         { threefry42((u32)(j - half), (u32)j, o0, o1); bits = o1; }
#else
  threefry42((u32)(j >> 32), (u32)j, o0, o1); bits = o0 ^ o1;
#endif
  float u = __uint_as_float((bits >> 9) | 0x3f800000u) - 1.0f;
  float v = fmaxf(1e-10f, u + 1e-10f);
  return -logf(-logf(v));
}

// ---------------- K1: per-slice max/sum/ssq + chunk maxima + sumexp ----------------
__global__ void __launch_bounds__(NTH, 1)
pass1_kernel(const float* __restrict__ logits, int V, int Vs)
{
  const int row = blockIdx.x / SPLIT, sl = blockIdx.x % SPLIT;
  const int tid = threadIdx.x, lane = tid & 31, wid = tid >> 5;
  const float* lrow = logits + (size_t)row * V;
  int e0 = sl * Vs; if (e0 > V) e0 = V;
  int e1 = e0 + Vs; if (e1 > V) e1 = V;
  const int f0 = e0 >> 2, f1 = e1 >> 2;
  const float4* l4 = (const float4*)lrow;
  __shared__ float rm[32], rs[32], rq[32];
  __shared__ float sh_bm;

  float m = __int_as_float(0xff800000), sum = 0.f, ssq = 0.f;
  const int iters = (f1 - f0 + NTH - 1) / NTH;
  for (int t = 0; t < iters; t++){
    int i = f0 + t * NTH + tid;
    bool in = (i < f1);
    float lm = __int_as_float(0xff800000);
    if (in){
      float4 v = l4[i];
      lm = fmaxf(fmaxf(v.x, v.y), fmaxf(v.z, v.w));
      sum += (v.x + v.y) + (v.z + v.w);
      ssq += v.x*v.x + v.y*v.y + v.z*v.z + v.w*v.w;
    }
    float cm = lm;
    #pragma unroll
    for (int o = 1; o < 8; o <<= 1) cm = fmaxf(cm, __shfl_xor_sync(~0u, cm, o));
    if ((lane & 7) == 0 && in) g_chmax[(size_t)row * MAXCHUNK + (i >> 3)] = cm;
    m = fmaxf(m, lm);
  }
  for (int i = (f1 << 2) + tid; i < e1; i += NTH){   // scalar tail (V%4)
    float x = lrow[i];
    m = fmaxf(m, x); sum += x; ssq += x * x;
  }
  // block-reduce max
  float mm = m;
  #pragma unroll
  for (int o = 16; o; o >>= 1) mm = fmaxf(mm, __shfl_down_sync(~0u, mm, o));
  if (lane == 0) rm[wid] = mm;
  __syncthreads();
  if (wid == 0){
    mm = rm[lane];
    #pragma unroll
    for (int o = 16; o; o >>= 1) mm = fmaxf(mm, __shfl_down_sync(~0u, mm, o));
    if (lane == 0) sh_bm = mm;
  }
  __syncthreads();
  const float bm = sh_bm;
  // pass B: sumexp with slice-max shift (slice is L1-resident)
  float se = 0.f;
  for (int t = 0; t < iters; t++){
    int i = f0 + t * NTH + tid;
    if (i < f1){
      float4 v = l4[i];
      se += __expf(v.x - bm) + __expf(v.y - bm) + __expf(v.z - bm) + __expf(v.w - bm);
    }
  }
  for (int i = (f1 << 2) + tid; i < e1; i += NTH) se += __expf(lrow[i] - bm);
  // block-reduce sum/ssq/se
  #pragma unroll
  for (int o = 16; o; o >>= 1){
    sum += __shfl_down_sync(~0u, sum, o);
    ssq += __shfl_down_sync(~0u, ssq, o);
    se  += __shfl_down_sync(~0u, se,  o);
  }
  if (lane == 0){ rm[wid] = sum; rs[wid] = ssq; rq[wid] = se; }
  __syncthreads();
  if (wid == 0){
    sum = rm[lane]; ssq = rs[lane]; se = rq[lane];
    #pragma unroll
    for (int o = 16; o; o >>= 1){
      sum += __shfl_down_sync(~0u, sum, o);
      ssq += __shfl_down_sync(~0u, ssq, o);
      se  += __shfl_down_sync(~0u, se,  o);
    }
    if (lane == 0){
      g_smax[row * SPLIT + sl] = bm;
      g_ssum[row * SPLIT + sl] = sum;
      g_sssq[row * SPLIT + sl] = ssq;
      g_sexp[row * SPLIT + sl] = se;
    }
  }
}

// ---------------- K2: per-row gather / penalties / selection / outputs ----------------
__global__ void __launch_bounds__(NTH, 1)
sampler_kernel(const float* __restrict__ logits, const float* __restrict__ temperature,
               const float* __restrict__ presence, const float* __restrict__ frequency,
               const float* __restrict__ repetition, const float* __restrict__ top_p,
               const int* __restrict__ prompt_ids, const int* __restrict__ out_tok,
               const int* __restrict__ out_lens, const int* __restrict__ stop_ids,
               const int* __restrict__ min_toks, const int* __restrict__ top_k,
               float* __restrict__ out, int B, int V, int P, int O, int S, int MN,
               int nchunk)
{
  extern __shared__ unsigned char smraw[];
  u64* cand = (u64*)smraw;              // CAP u64 (reused as survivor buffer)
  u32* hkey = (u32*)(cand + CAP);       // HCAP
  u32* hval = hkey + HCAP;              // HCAP
  float* chm = (float*)(hval + HCAP);   // nchunk
  __shared__ u64 red64[32];
  __shared__ volatile u64 sh_win;
  __shared__ float sh_m, sh_logs, sh_T, sh_lo, sh_hi;
  __shared__ int sh_cnt;

  const int tid = threadIdx.x, row = blockIdx.x;
  const int lane = tid & 31, wid = tid >> 5;
  const float* lrow = logits + (size_t)row * V;
  const int n4 = V >> 2;
  const float4* l4 = (const float4*)lrow;

  // penalty-state hash: bits[0:16) count, bit16 prompt, bit17 stop-neg
  for (int i = tid; i < HCAP; i += NTH){ hkey[i] = 0xFFFFFFFFu; hval[i] = 0u; }
  // chunk maxima -> smem
  for (int i = tid; i < nchunk; i += NTH) chm[i] = g_chmax[(size_t)row * MAXCHUNK + i];
  // per-row stats from slice partials
  if (tid == 0){
    float m = __int_as_float(0xff800000), sum = 0.f, ssq = 0.f;
    float ms[SPLIT];
    for (int s2 = 0; s2 < SPLIT; s2++){
      ms[s2] = g_smax[row * SPLIT + s2];
      m = fmaxf(m, ms[s2]);
      sum += g_ssum[row * SPLIT + s2];
      ssq += g_sssq[row * SPLIT + s2];
    }
    float Z = 0.f;
    for (int s2 = 0; s2 < SPLIT; s2++) Z += g_sexp[row * SPLIT + s2] * __expf(ms[s2] - m);
    sh_m = m; sh_logs = logf(Z);
    float mu = sum / (float)V;
    float sig = sqrtf(fmaxf(ssq / (float)V - mu * mu, 0.f));
    float lo = mu - 4.0f * sig - 1e-6f, hi = m, T = mu + 2.0f * sig;
    if (!(T > lo)) T = lo;
    if (T > hi) T = 0.5f * (lo + hi);
    sh_lo = lo; sh_hi = hi; sh_T = T;
  }
  __syncthreads();

  const int olen = out_lens[row];
  const bool penal = olen < min_toks[row];
  auto insert = [&](int id, u32 orb, u32 add){
    u32 uid = (u32)id, h = ((uid * 2654435761u) >> 16) & (HCAP - 1);
    for (;;){
      u32 k = hkey[h];
      if (k == uid) break;
      if (k == 0xFFFFFFFFu){
        u32 old = atomicCAS(&hkey[h], 0xFFFFFFFFu, uid);
        if (old == 0xFFFFFFFFu || old == uid) break;
      }
      h = (h + 1) & (HCAP - 1);
    }
    if (orb) atomicOr(&hval[h], orb);
    if (add) atomicAdd(&hval[h], add);
  };
  for (int i = tid; i < P; i += NTH) insert(prompt_ids[(size_t)row*P + i], 1u<<16, 0u);
  for (int i = tid; i < O; i += NTH) if (i < olen) insert(out_tok[(size_t)row*O + i], 0u, 1u);
  if (penal) for (int i = tid; i < S; i += NTH) insert(stop_ids[(size_t)row*S + i], 1u<<17, 0u);
  __syncthreads();

  // threshold-gather with chunk-skip (bisection fallback)
  int minc = P + O + S + TOPN;
  if (minc > V) minc = V;
  const int iters = (n4 + NTH - 1) / NTH;
  int c = 0;
  for (int it = 0; it < 40; it++){
    if (tid == 0) sh_cnt = 0;
    __syncthreads();
    const float T = sh_T;
    for (int t = 0; t < iters; t++){
      int i = t * NTH + tid;
      bool in = (i < n4) && (chm[(i < n4 ? i : 0) >> 3] >= T);
      float4 v = in ? l4[i] : make_float4(NEG_INF_F, NEG_INF_F, NEG_INF_F, NEG_INF_F);
      float xs[4] = {v.x, v.y, v.z, v.w};
      u32 mk[4]; int pc[4];
      #pragma unroll
      for (int c2 = 0; c2 < 4; c2++){
        mk[c2] = __ballot_sync(~0u, in && (xs[c2] >= T));
        pc[c2] = __popc(mk[c2]);
      }
      int total = pc[0] + pc[1] + pc[2] + pc[3];
      if (total){
        int base = 0;
        if (lane == 0) base = atomicAdd(&sh_cnt, total);
        base = __shfl_sync(~0u, base, 0);
        int run = 0, bi = i << 2;
        u32 lt = (1u << lane) - 1u;
        #pragma unroll
        for (int c2 = 0; c2 < 4; c2++){
          if (mk[c2] & (1u << lane)){
            int p = base + run + __popc(mk[c2] & lt);
            if (p < CAP) cand[p] = ((u64)fkey(xs[c2]) << 32) | (u32)~(u32)(bi + c2);
          }
          run += pc[c2];
        }
      }
    }
    for (int i = (n4<<2) + tid; i < V; i += NTH){
      float x = lrow[i];
      if (x >= T){ int p = atomicAdd(&sh_cnt,1); if (p < CAP) cand[p] = ((u64)fkey(x)<<32) | (u32)~(u32)i; }
    }
    __syncthreads();
    c = sh_cnt;
    if (c >= minc && c <= CAP) break;
    if (tid == 0){ if (c > CAP) sh_lo = sh_T; else sh_hi = sh_T; sh_T = 0.5f*(sh_lo + sh_hi); }
    __syncthreads();
  }
  if (c > CAP) c = CAP;

  u64 rk[LOCAL];
  #pragma unroll
  for (int q = 0; q < LOCAL; q++){ int p = q*NTH + tid; rk[q] = (p < c) ? cand[p] : 0ULL; }
  const float mrow = sh_m, logZ = sh_logs;

  // raw top-MN -> logprobs + indices
  u32 rmask = 0;
  const int mrounds = (MN < c) ? MN : c;
  for (int r = 0; r < mrounds; r++){
    u64 b = 0;
    #pragma unroll
    for (int q = 0; q < LOCAL; q++) if (!((rmask>>q)&1u) && rk[q] > b) b = rk[q];
    u64 v = b;
    #pragma unroll
    for (int o = 16; o; o >>= 1){ u64 t = __shfl_down_sync(~0u, v, o); if (t > v) v = t; }
    if (lane == 0) red64[wid] = v;
    __syncthreads();
    if (wid == 0){
      u64 w = red64[lane];
      #pragma unroll
      for (int o = 16; o; o >>= 1){ u64 t = __shfl_down_sync(~0u, w, o); if (t > w) w = t; }
      if (lane == 0) sh_win = w;
    }
    __syncthreads();
    u64 win = sh_win;
    if (tid == 0){
      out[(size_t)B + (size_t)row*MN + r] = (fdec((u32)(win>>32)) - mrow) - logZ;
      out[(size_t)B + (size_t)B*MN + (size_t)row*MN + r] = (float)(~(u32)win);
    }
    #pragma unroll
    for (int q = 0; q < LOCAL; q++) if (rk[q] == win) rmask |= (1u<<q);
  }
  if (tid == 0) for (int r = mrounds; r < MN; r++){
    out[(size_t)B + (size_t)row*MN + r] = 0.f;
    out[(size_t)B + (size_t)B*MN + (size_t)row*MN + r] = 0.f;
  }

  // transform candidates in registers: penalties + temperature (non-increasing)
  const float rep = repetition[row], fr = frequency[row], pr = presence[row];
  const float tp = temperature[row], td = (tp < 1e-5f) ? 1.f : tp;
  #pragma unroll
  for (int q = 0; q < LOCAL; q++){
    u64 k = rk[q];
    if (k != 0ULL){
      u32 idx = ~(u32)k;
      float x = fdec((u32)(k >> 32));
      u32 h = ((idx * 2654435761u) >> 16) & (HCAP - 1), info = 0;
      for (;;){
        u32 kk = hkey[h];
        if (kk == idx){ info = hval[h]; break; }
        if (kk == 0xFFFFFFFFu) break;
        h = (h + 1) & (HCAP - 1);
      }
      int cv = (int)(info & 0xFFFFu);
      if (info & (1u<<17)) x = NEG_INF_F;
      if ((info & (1u<<16)) || cv > 0) x = (x > 0.f) ? (x / rep) : (x * rep);
      x = x - fr * (float)cv;
      if (cv > 0) x = x - pr;
      x = x / td;
      rk[q] = ((u64)fkey(x) << 32) | (u32)~idx;
    }
  }
  __syncthreads();   // cand[] free from here

  // bisect value-key threshold so survivor count in [need, SSZ]
  const int need = (TOPN < c) ? TOPN : c;
  u32 Tsel = 1u;
  if (c > SSZ){
    u32 blo = 0, bhi = 0xFFFFFFFFu, best = 0;
    for (int it = 0; it < 34; it++){
      u32 mid = blo + ((bhi - blo) >> 1);
      if (tid == 0) sh_cnt = 0;
      __syncthreads();
      int cnt = 0;
      #pragma unroll
      for (int q = 0; q < LOCAL; q++)
        if (rk[q] && (u32)(rk[q] >> 32) >= mid) cnt++;
      #pragma unroll
      for (int o = 16; o; o >>= 1) cnt += __shfl_down_sync(~0u, cnt, o);
      if (lane == 0 && cnt) atomicAdd(&sh_cnt, cnt);
      __syncthreads();
      int total = sh_cnt;
      if (total >= need && mid > best) best = mid;
      if (total >= need && total <= SSZ){ best = mid; break; }
      if (total > SSZ) blo = mid + 1; else { if (mid == 0) break; bhi = mid - 1; }
      if (blo > bhi) break;
    }
    Tsel = best;
  }

  // gather survivors into cand[0..SSZ)
  if (tid == 0) sh_cnt = 0;
  __syncthreads();
  #pragma unroll
  for (int q = 0; q < LOCAL; q++){
    bool pred = rk[q] && (u32)(rk[q] >> 32) >= Tsel;
    u32 mk = __ballot_sync(~0u, pred);
    if (mk){
      int leader = __ffs(mk) - 1, pos = 0;
      if (lane == leader) pos = atomicAdd(&sh_cnt, __popc(mk));
      pos = __shfl_sync(~0u, pos, leader);
      if (pred){
        int p = pos + __popc(mk & ((1u << lane) - 1u));
        if (p < SSZ) cand[p] = rk[q];
      }
    }
  }
  __syncthreads();
  int sc = sh_cnt; if (sc > SSZ) sc = SSZ;
  for (int p = tid; p < SSZ; p += NTH) if (p >= sc) cand[p] = 0ULL;

  // bitonic ascending sort of cand[0..SSZ)
  for (int kk = 2; kk <= SSZ; kk <<= 1)
    for (int j = kk >> 1; j > 0; j >>= 1){
      __syncthreads();
      if (tid < SSZ){
        int l = tid ^ j;
        if (l > tid){
          u64 a = cand[tid], b2 = cand[l];
          bool asc = ((tid & kk) == 0);
          if (asc ? (a > b2) : (a < b2)){ cand[tid] = b2; cand[l] = a; }
        }
      }
    }
  __syncthreads();

  // epilogue: top-k mask, top-p mask, gumbel-argmax (thread 0)
  if (tid == 0){
    const int trounds = (TOPN < c) ? TOPN : c;
    int k = top_k[row];
    if (k < 1) k = 1;
    if (k > trounds) k = trounds;
    float kth = fdec((u32)(cand[SSZ - k] >> 32));
    float m0  = fdec((u32)(cand[SSZ - 1] >> 32));
    float Ssum = 0.f; int k2 = 0;
    for (int j = 0; j < trounds; j++){
      float x = fdec((u32)(cand[SSZ-1-j] >> 32));
      if (x >= kth){ Ssum += expf(x - m0); k2 = j + 1; } else break;
    }
    const float thr = top_p[row] * Ssum;
    const u64 half = ((u64)B * (u64)V) >> 1;
    float pref = 0.f, best = __int_as_float(0xff800000);
    u32 besti = ~(u32)cand[SSZ - 1];
    for (int j = 0; j < k2; j++){
      u64 w = cand[SSZ-1-j];
      float x = fdec((u32)(w >> 32));
      u32 ix = ~(u32)w;
      bool keep = (j == 0) || (pref < thr);
      pref += expf(x - m0);
      if (keep){
        float sc2 = x + gumbel_at((u64)row * (u64)V + ix, half);
        if (sc2 > best){ best = sc2; besti = ix; }
      }
    }
    out[row] = (float)((tp < 1e-5f) ? (~(u32)cand[SSZ - 1]) : besti);
  }
}

extern "C" void kernel_launch(void* const* d_in, const int* in_sizes, int n_in,
                              void* d_out, int out_size)
{
  const float* logits = (const float*)d_in[0];
  int B = in_sizes[1];
  int V = in_sizes[0] / B;
  int P = in_sizes[6] / B;
  int O = in_sizes[7] / B;
  int S = in_sizes[9] / B;
  int MN = (out_size / B - 1) / 2;
  if (MN < 0) MN = 0;
  int n4 = V >> 2;
  int nchunk = (n4 + 7) >> 3;
  int Vs = (((V + SPLIT - 1) / SPLIT) + 31) & ~31;

  pass1_kernel<<<B * SPLIT, NTH>>>(logits, V, Vs);

  size_t sh = (size_t)CAP * sizeof(u64) + (size_t)HCAP * 2 * sizeof(u32)
            + (size_t)nchunk * sizeof(float);
  cudaFuncSetAttribute(sampler_kernel, cudaFuncAttributeMaxDynamicSharedMemorySize, (int)sh);
  sampler_kernel<<<B, NTH, sh>>>(logits,
      (const float*)d_in[1], (const float*)d_in[2], (const float*)d_in[3],
      (const float*)d_in[4], (const float*)d_in[5],
      (const int*)d_in[6], (const int*)d_in[7], (const int*)d_in[8],
      (const int*)d_in[9], (const int*)d_in[10], (const int*)d_in[11],
      (float*)d_out, B, V, P, O, S, MN, nchunk);
}